// round 2
// baseline (speedup 1.0000x reference)
#include <cuda_runtime.h>
#include <cstdint>

#define N_NODES 50000
#define F_IN    256
#define F_OUT   64

// Scratch for projected features XW (12.8 MB) — static device global (no-alloc rule).
__device__ float g_XW[(size_t)N_NODES * F_OUT];

union F2U { float2 f; unsigned long long u; };

// Packed dual-FMA: d = a * b + d on two fp32 lanes (SASS: FFMA2, 2x fp32 rate).
__device__ __forceinline__ void fma2(unsigned long long& d,
                                     unsigned long long a,
                                     unsigned long long b) {
    asm volatile("fma.rn.f32x2 %0, %1, %2, %3;"
                 : "=l"(d) : "l"(a), "l"(b), "l"(d));
}

// ---------------------------------------------------------------------------
// Stage 1: XW = X @ W   (50000 x 256) @ (256 x 64), fp32 via f32x2 packed FMA.
// Block tile 128x64, BK=32, 128 threads. Per-thread micro-tile 16x4 stored as
// 8x4 f32x2 accumulators (pairs along M). B tile pre-duplicated {b,b} in smem
// so the inner loop has no pack MOVs.
// ---------------------------------------------------------------------------
#define BM 128
#define BN 64
#define BK 32
#define AP 130   // A tile row pad: 2-way max bank conflict on stores, keeps 8B align

__global__ __launch_bounds__(128) void gemm_kernel(const float* __restrict__ X,
                                                   const float* __restrict__ W) {
    __shared__ float As[BK][AP];                 // [k][m], m contiguous for pair LDS.64
    __shared__ unsigned long long Bs2[BK][BN];   // duplicated {b,b}

    const int t  = threadIdx.x;
    const int tx = t & 15;   // 16 col groups * 4  = 64 cols
    const int ty = t >> 4;   //  8 row groups * 16 = 128 rows
    const int rowBase = blockIdx.x * BM;

    unsigned long long acc[8][4];
#pragma unroll
    for (int p = 0; p < 8; p++)
#pragma unroll
        for (int j = 0; j < 4; j++) acc[p][j] = 0ull;

    for (int k0 = 0; k0 < F_IN; k0 += BK) {
        // A tile: 128 rows x 32 k = 1024 float4, 8 per thread (coalesced on k)
#pragma unroll
        for (int i = 0; i < 8; i++) {
            int f   = t + i * 128;     // 0..1023
            int m   = f >> 3;          // row in tile
            int kk4 = f & 7;           // float4 slot along k
            int gr  = rowBase + m;
            if (gr >= N_NODES) gr = N_NODES - 1;   // clamp (last block only)
            float4 v = *(const float4*)(X + (size_t)gr * F_IN + k0 + kk4 * 4);
            As[kk4 * 4 + 0][m] = v.x;
            As[kk4 * 4 + 1][m] = v.y;
            As[kk4 * 4 + 2][m] = v.z;
            As[kk4 * 4 + 3][m] = v.w;
        }
        // B tile: 32 k x 64 n = 512 float4, 4 per thread, stored duplicated
#pragma unroll
        for (int i = 0; i < 4; i++) {
            int f  = t + i * 128;
            int kk = f >> 4;
            int n4 = f & 15;
            float4 v = *(const float4*)(W + (size_t)(k0 + kk) * F_OUT + n4 * 4);
            F2U u;
            u.f = make_float2(v.x, v.x); Bs2[kk][n4 * 4 + 0] = u.u;
            u.f = make_float2(v.y, v.y); Bs2[kk][n4 * 4 + 1] = u.u;
            u.f = make_float2(v.z, v.z); Bs2[kk][n4 * 4 + 2] = u.u;
            u.f = make_float2(v.w, v.w); Bs2[kk][n4 * 4 + 3] = u.u;
        }
        __syncthreads();

#pragma unroll
        for (int k = 0; k < BK; k++) {
            const float2* ar = (const float2*)&As[k][ty * 16];  // 8B-aligned
            unsigned long long a2[8], b2[4];
#pragma unroll
            for (int p = 0; p < 8; p++) { F2U u; u.f = ar[p]; a2[p] = u.u; }
#pragma unroll
            for (int j = 0; j < 4; j++) b2[j] = Bs2[k][tx * 4 + j];
#pragma unroll
            for (int p = 0; p < 8; p++)
#pragma unroll
                for (int j = 0; j < 4; j++)
                    fma2(acc[p][j], a2[p], b2[j]);
        }
        __syncthreads();
    }

    // Store: each f32x2 pair holds rows (m0, m0+1) of one column.
#pragma unroll
    for (int p = 0; p < 8; p++) {
        int m0 = rowBase + ty * 16 + 2 * p;
        F2U u0, u1, u2, u3;
        u0.u = acc[p][0]; u1.u = acc[p][1]; u2.u = acc[p][2]; u3.u = acc[p][3];
        if (m0 < N_NODES) {
            float4 lo = make_float4(u0.f.x, u1.f.x, u2.f.x, u3.f.x);
            *(float4*)(g_XW + (size_t)m0 * F_OUT + tx * 4) = lo;
        }
        if (m0 + 1 < N_NODES) {
            float4 hi = make_float4(u0.f.y, u1.f.y, u2.f.y, u3.f.y);
            *(float4*)(g_XW + (size_t)(m0 + 1) * F_OUT + tx * 4) = hi;
        }
    }
}

// ---------------------------------------------------------------------------
// Stage 2: out[row] += val * XW[col] over E edges.
// 16 threads per edge-group; each thread processes 4 edges' same float4 slot:
// 4 independent LDG.128 gathers in flight (MLP=4), then 4 red.global.add.v4.f32.
// ---------------------------------------------------------------------------
__device__ __forceinline__ void red4(float* dst, float s, float4 x) {
    asm volatile("red.global.add.v4.f32 [%0], {%1, %2, %3, %4};"
                 :: "l"(dst), "f"(s * x.x), "f"(s * x.y), "f"(s * x.z), "f"(s * x.w)
                 : "memory");
}

__global__ __launch_bounds__(256) void scatter_kernel(const int*   __restrict__ erow,
                                                      const int*   __restrict__ ecol,
                                                      const float* __restrict__ evals,
                                                      float*       __restrict__ out,
                                                      int E) {
    int idx = blockIdx.x * 256 + threadIdx.x;
    int g = idx >> 4;         // edge quad index
    int l = idx & 15;         // float4 slot within the 64-wide feature row
    int e0 = g * 4;
    if (e0 >= E) return;

    if (e0 + 4 <= E) {
        int4   r4 = *(const int4*)(erow + e0);
        int4   c4 = *(const int4*)(ecol + e0);
        float4 v4 = *(const float4*)(evals + e0);

        // issue all gathers first (independent -> MLP=4)
        float4 x0 = ((const float4*)(g_XW + (size_t)c4.x * F_OUT))[l];
        float4 x1 = ((const float4*)(g_XW + (size_t)c4.y * F_OUT))[l];
        float4 x2 = ((const float4*)(g_XW + (size_t)c4.z * F_OUT))[l];
        float4 x3 = ((const float4*)(g_XW + (size_t)c4.w * F_OUT))[l];

        red4(out + (size_t)r4.x * F_OUT + l * 4, v4.x, x0);
        red4(out + (size_t)r4.y * F_OUT + l * 4, v4.y, x1);
        red4(out + (size_t)r4.z * F_OUT + l * 4, v4.z, x2);
        red4(out + (size_t)r4.w * F_OUT + l * 4, v4.w, x3);
    } else {
        for (int e = e0; e < E; e++) {
            int   r = erow[e], c = ecol[e];
            float v = evals[e];
            float4 x = ((const float4*)(g_XW + (size_t)c * F_OUT))[l];
            red4(out + (size_t)r * F_OUT + l * 4, v, x);
        }
    }
}

// ---------------------------------------------------------------------------
// Launch (graph-capturable: memset node + 2 kernel nodes)
// ---------------------------------------------------------------------------
extern "C" void kernel_launch(void* const* d_in, const int* in_sizes, int n_in,
                              void* d_out, int out_size) {
    const float* X     = (const float*)d_in[0];
    const float* W     = (const float*)d_in[1];
    const int*   erow  = (const int*)d_in[2];
    const int*   ecol  = (const int*)d_in[3];
    const float* evals = (const float*)d_in[4];
    float*       out   = (float*)d_out;
    const int E = in_sizes[2];

    cudaMemsetAsync(d_out, 0, (size_t)out_size * sizeof(float), 0);

    gemm_kernel<<<(N_NODES + BM - 1) / BM, 128>>>(X, W);

    int groups  = (E + 3) / 4;
    long long threads = (long long)groups * 16;
    int blocks  = (int)((threads + 255) / 256);
    scatter_kernel<<<blocks, 256>>>(erow, ecol, evals, out, E);
}

// round 6
// speedup vs baseline: 1.4276x; 1.4276x over previous
#include <cuda_runtime.h>
#include <cstdint>

#define N_NODES 50000
#define F_IN    256
#define F_OUT   64

// Scratch for projected features XW (12.8 MB) — static device global (no-alloc rule).
__device__ float g_XW[(size_t)N_NODES * F_OUT];

__device__ __forceinline__ uint32_t f2tf32(float x) {
    uint32_t r;
    asm("cvt.rna.tf32.f32 %0, %1;" : "=r"(r) : "f"(x));
    return r;
}

// ---------------------------------------------------------------------------
// Stage 1: XW = X @ W via mma.sync.m16n8k8 tf32 (baseline PTX, valid on sm_103).
// Block: 128 rows x 64 cols, 256 threads (8 warps). Whole K=256 resident in
// smem (A 128x260f, B 256x72f = 207 KB, 1 CTA/SM). Each warp: 16 rows x 64
// cols = 32 K-steps x 8 N-tiles of m16n8k8.
// Strides: A_STRIDE=260 (mod32=4), B_STRIDE=72 (mod32=8) -> conflict-free
// fragment loads (all 32 lanes hit distinct banks).
// ---------------------------------------------------------------------------
#define A_STRIDE 260
#define B_STRIDE 72
#define SMEM_A_FLOATS (128 * A_STRIDE)
#define SMEM_B_FLOATS (256 * B_STRIDE)
#define GEMM_SMEM_BYTES ((SMEM_A_FLOATS + SMEM_B_FLOATS) * 4)   // 206848 B

__global__ __launch_bounds__(256, 1) void gemm_mma_kernel(const float* __restrict__ X,
                                                          const float* __restrict__ W) {
    extern __shared__ float sm[];
    float* As = sm;                       // [128][260] tf32 bit patterns
    float* Bs = sm + SMEM_A_FLOATS;       // [256][72]

    const int t = threadIdx.x;
    const int rowBase = blockIdx.x * 128;

    // ---- Fill A: 128 rows x 256 k = 8192 float4, 32 per thread (coalesced on k)
#pragma unroll
    for (int i = 0; i < 32; i++) {
        int f = t + i * 256;          // 0..8191
        int m = f >> 6;               // row in tile (64 float4 per row)
        int q = f & 63;               // float4 slot along k
        int gr = rowBase + m;
        if (gr >= N_NODES) gr = N_NODES - 1;      // clamp; stores guarded later
        float4 v = *(const float4*)(X + (size_t)gr * F_IN + q * 4);
        uint32_t* dst = (uint32_t*)(As + m * A_STRIDE + q * 4);
        dst[0] = f2tf32(v.x); dst[1] = f2tf32(v.y);
        dst[2] = f2tf32(v.z); dst[3] = f2tf32(v.w);
    }
    // ---- Fill B: 256 k x 64 n = 4096 float4, 16 per thread (coalesced on n)
#pragma unroll
    for (int i = 0; i < 16; i++) {
        int f  = t + i * 256;         // 0..4095
        int k  = f >> 4;
        int n4 = f & 15;
        float4 v = *(const float4*)(W + (size_t)k * F_OUT + n4 * 4);
        uint32_t* dst = (uint32_t*)(Bs + k * B_STRIDE + n4 * 4);
        dst[0] = f2tf32(v.x); dst[1] = f2tf32(v.y);
        dst[2] = f2tf32(v.z); dst[3] = f2tf32(v.w);
    }
    __syncthreads();

    const int w    = t >> 5;
    const int lane = t & 31;
    const int gid  = lane >> 2;     // 0..7  (row group)
    const int tig  = lane & 3;      // 0..3  (thread in group)

    float c[8][4];
#pragma unroll
    for (int nt = 0; nt < 8; nt++)
#pragma unroll
        for (int j = 0; j < 4; j++) c[nt][j] = 0.f;

    const float* arow0 = As + (w * 16 + gid) * A_STRIDE;   // rows gid / gid+8
    const float* arow1 = arow0 + 8 * A_STRIDE;

#pragma unroll 4
    for (int ks = 0; ks < 32; ks++) {
        const int kc = ks * 8 + tig;
        // A fragment (m16k8 tf32): a0=(gid,kc) a1=(gid+8,kc) a2=(gid,kc+4) a3=(gid+8,kc+4)
        uint32_t a0 = *(const uint32_t*)(arow0 + kc);
        uint32_t a1 = *(const uint32_t*)(arow1 + kc);
        uint32_t a2 = *(const uint32_t*)(arow0 + kc + 4);
        uint32_t a3 = *(const uint32_t*)(arow1 + kc + 4);

        const float* b_lo = Bs + (size_t)kc * B_STRIDE;        // row kc
        const float* b_hi = b_lo + 4 * B_STRIDE;               // row kc+4
#pragma unroll
        for (int nt = 0; nt < 8; nt++) {
            // B fragment (k8n8): b0=(tig, nt*8+gid) b1=(tig+4, nt*8+gid)
            uint32_t b0 = *(const uint32_t*)(b_lo + nt * 8 + gid);
            uint32_t b1 = *(const uint32_t*)(b_hi + nt * 8 + gid);
            asm volatile(
                "mma.sync.aligned.m16n8k8.row.col.f32.tf32.tf32.f32 "
                "{%0,%1,%2,%3}, {%4,%5,%6,%7}, {%8,%9}, {%0,%1,%2,%3};"
                : "+f"(c[nt][0]), "+f"(c[nt][1]), "+f"(c[nt][2]), "+f"(c[nt][3])
                : "r"(a0), "r"(a1), "r"(a2), "r"(a3), "r"(b0), "r"(b1));
        }
    }

    // ---- Epilogue: c0,c1 at (row0, 2*tig), c2,c3 at (row0+8, 2*tig) per n-tile
    const int r0 = rowBase + w * 16 + gid;
    const int r1 = r0 + 8;
#pragma unroll
    for (int nt = 0; nt < 8; nt++) {
        int col = nt * 8 + 2 * tig;
        if (r0 < N_NODES)
            *(float2*)(g_XW + (size_t)r0 * F_OUT + col) = make_float2(c[nt][0], c[nt][1]);
        if (r1 < N_NODES)
            *(float2*)(g_XW + (size_t)r1 * F_OUT + col) = make_float2(c[nt][2], c[nt][3]);
    }
}

// ---------------------------------------------------------------------------
// Stage 2: out[row] += val * XW[col] over E edges. 16 threads per edge-quad,
// MLP=4 gathers then 4 red.global.add.v4.f32. (measured 39.4 us, near L2 cap)
// ---------------------------------------------------------------------------
__device__ __forceinline__ void red4(float* dst, float s, float4 x) {
    asm volatile("red.global.add.v4.f32 [%0], {%1, %2, %3, %4};"
                 :: "l"(dst), "f"(s * x.x), "f"(s * x.y), "f"(s * x.z), "f"(s * x.w)
                 : "memory");
}

__global__ __launch_bounds__(256) void scatter_kernel(const int*   __restrict__ erow,
                                                      const int*   __restrict__ ecol,
                                                      const float* __restrict__ evals,
                                                      float*       __restrict__ out,
                                                      int E) {
    int idx = blockIdx.x * 256 + threadIdx.x;
    int g = idx >> 4;
    int l = idx & 15;
    int e0 = g * 4;
    if (e0 >= E) return;

    if (e0 + 4 <= E) {
        int4   r4 = *(const int4*)(erow + e0);
        int4   c4 = *(const int4*)(ecol + e0);
        float4 v4 = *(const float4*)(evals + e0);

        float4 x0 = ((const float4*)(g_XW + (size_t)c4.x * F_OUT))[l];
        float4 x1 = ((const float4*)(g_XW + (size_t)c4.y * F_OUT))[l];
        float4 x2 = ((const float4*)(g_XW + (size_t)c4.z * F_OUT))[l];
        float4 x3 = ((const float4*)(g_XW + (size_t)c4.w * F_OUT))[l];

        red4(out + (size_t)r4.x * F_OUT + l * 4, v4.x, x0);
        red4(out + (size_t)r4.y * F_OUT + l * 4, v4.y, x1);
        red4(out + (size_t)r4.z * F_OUT + l * 4, v4.z, x2);
        red4(out + (size_t)r4.w * F_OUT + l * 4, v4.w, x3);
    } else {
        for (int e = e0; e < E; e++) {
            int   r = erow[e], c = ecol[e];
            float v = evals[e];
            float4 x = ((const float4*)(g_XW + (size_t)c * F_OUT))[l];
            red4(out + (size_t)r * F_OUT + l * 4, v, x);
        }
    }
}

// ---------------------------------------------------------------------------
// Launch (graph-capturable: memset node + 2 kernel nodes)
// ---------------------------------------------------------------------------
extern "C" void kernel_launch(void* const* d_in, const int* in_sizes, int n_in,
                              void* d_out, int out_size) {
    const float* X     = (const float*)d_in[0];
    const float* W     = (const float*)d_in[1];
    const int*   erow  = (const int*)d_in[2];
    const int*   ecol  = (const int*)d_in[3];
    const float* evals = (const float*)d_in[4];
    float*       out   = (float*)d_out;
    const int E = in_sizes[2];

    cudaMemsetAsync(d_out, 0, (size_t)out_size * sizeof(float), 0);

    cudaFuncSetAttribute(gemm_mma_kernel, cudaFuncAttributeMaxDynamicSharedMemorySize,
                         GEMM_SMEM_BYTES);
    gemm_mma_kernel<<<(N_NODES + 127) / 128, 256, GEMM_SMEM_BYTES>>>(X, W);

    int groups = (E + 3) / 4;
    long long threads = (long long)groups * 16;
    int blocks = (int)((threads + 255) / 256);
    scatter_kernel<<<blocks, 256>>>(erow, ecol, evals, out, E);
}